// round 1
// baseline (speedup 1.0000x reference)
#include <cuda_runtime.h>
#include <cstdint>

// Input:  x  (4, 64, 512, 512) fp32  -> flatten (BC=256, 512, 512)
// Output: [ll | lh | hl | hh], each (256, 256, 256) fp32, concatenated.
//
// Each thread: reads float4 from row 2h and row 2h+1 (covering a 2x4 input
// patch = two 2x2 blocks), writes a float2 into each of the 4 output planes.

static constexpr int BC    = 256;          // 4 * 64
static constexpr int W_IN  = 512;
static constexpr int H_OUT = 256;
static constexpr int W_OUT = 256;
static constexpr int PLANE = BC * H_OUT * W_OUT;        // 16,777,216 elems per plane
static constexpr long long TOTAL_PAIRS = (long long)BC * H_OUT * (W_OUT / 2); // 8,388,608

__global__ void __launch_bounds__(256) fast_dwt_kernel(
    const float4* __restrict__ x,   // input viewed as float4 (128 per row of 512)
    float* __restrict__ out)
{
    long long idx = (long long)blockIdx.x * blockDim.x + threadIdx.x;
    if (idx >= TOTAL_PAIRS) return;

    // Decompose: idx -> (bc, ho, wq) where wq indexes float4 quads (128/row-pair)
    const int W4 = W_IN / 4;            // 128 float4 per input row
    int wq = (int)(idx % W4);
    long long t = idx / W4;
    int ho = (int)(t % H_OUT);
    int bc = (int)(t / H_OUT);

    // Input rows 2*ho and 2*ho+1, as float4 pointers.
    long long row0 = ((long long)bc * 512 + 2 * ho) * W4;   // in float4 units
    float4 r0 = x[row0 + wq];
    float4 r1 = x[row0 + W4 + wq];

    // Block 0: a=r0.x b=r0.y c=r1.x d=r1.y ; Block 1: a=r0.z b=r0.w c=r1.z d=r1.w
    float2 ll, lh, hl, hh;
    {
        float a = r0.x, b = r0.y, c = r1.x, d = r1.y;
        float apb = a + b, amb = a - b, cpd = c + d, cmd = c - d;
        ll.x = (apb + cpd) * 0.5f;
        lh.x = (apb - cpd) * 0.5f;
        hl.x = (amb + cmd) * 0.5f;
        hh.x = (amb - cmd) * 0.5f;
    }
    {
        float a = r0.z, b = r0.w, c = r1.z, d = r1.w;
        float apb = a + b, amb = a - b, cpd = c + d, cmd = c - d;
        ll.y = (apb + cpd) * 0.5f;
        lh.y = (apb - cpd) * 0.5f;
        hl.y = (amb + cmd) * 0.5f;
        hh.y = (amb - cmd) * 0.5f;
    }

    // Output offset within a plane (in floats): bc*H_OUT*W_OUT + ho*W_OUT + 2*wq
    long long o = ((long long)bc * H_OUT + ho) * W_OUT + 2 * wq;
    float2* ll_p = (float2*)(out + 0LL * PLANE + o);
    float2* lh_p = (float2*)(out + 1LL * PLANE + o);
    float2* hl_p = (float2*)(out + 2LL * PLANE + o);
    float2* hh_p = (float2*)(out + 3LL * PLANE + o);
    *ll_p = ll;
    *lh_p = lh;
    *hl_p = hl;
    *hh_p = hh;
}

extern "C" void kernel_launch(void* const* d_in, const int* in_sizes, int n_in,
                              void* d_out, int out_size)
{
    const float4* x = (const float4*)d_in[0];
    float* out = (float*)d_out;

    const int threads = 256;
    const long long nthreads = TOTAL_PAIRS;
    const int blocks = (int)((nthreads + threads - 1) / threads);
    fast_dwt_kernel<<<blocks, threads>>>(x, out);
}